// round 14
// baseline (speedup 1.0000x reference)
#include <cuda_runtime.h>
#include <cuda_fp16.h>
#include <cstdint>
#include <cstddef>

#define NN    8192
#define INF_  512
#define OUTF  256
#define ALPHA 0.2f

typedef unsigned long long u64;
typedef unsigned int u32;

// ---------------- scratch globals (no allocs allowed) ----------------
__device__ float g_s1[NN];
__device__ float g_s2[NN];
__device__ float g_e1p[NN];   // exp(s1)
__device__ float g_e1n[NN];   // exp(ALPHA*s1)
__device__ float g_e2p[NN];   // exp(s2)
__device__ float g_e2n[NN];   // exp(ALPHA*s2)
// h as fp16, PRE-SWIZZLED B-layout: byte(j,n) = j*512 + (((n>>3)^(j&7))<<4) + (n&7)*2
__device__ __align__(16) unsigned char g_hh[(size_t)NN * 512];
// W as fp16, PRE-SWIZZLED B-layout per 128-k tile
__device__ __align__(16) unsigned char g_wh[(size_t)INF_ * 512];

// ---------------- mma / ldmatrix / cp.async / barrier helpers ----------------
__device__ __forceinline__ u32 smem_u32(const void* p) {
    u32 a;
    asm("{ .reg .u64 t; cvta.to.shared.u64 t, %1; cvt.u32.u64 %0, t; }"
        : "=r"(a) : "l"(p));
    return a;
}
__device__ __forceinline__ void ldsm4(u32* r, u32 addr) {
    asm volatile("ldmatrix.sync.aligned.m8n8.x4.shared.b16 {%0,%1,%2,%3}, [%4];"
                 : "=r"(r[0]), "=r"(r[1]), "=r"(r[2]), "=r"(r[3]) : "r"(addr));
}
__device__ __forceinline__ void ldsm4t(u32* r, u32 addr) {
    asm volatile("ldmatrix.sync.aligned.m8n8.x4.trans.shared.b16 {%0,%1,%2,%3}, [%4];"
                 : "=r"(r[0]), "=r"(r[1]), "=r"(r[2]), "=r"(r[3]) : "r"(addr));
}
__device__ __forceinline__ void mma16816(float* d, const u32* a, const u32* b) {
    asm volatile(
        "mma.sync.aligned.m16n8k16.row.col.f32.f16.f16.f32 "
        "{%0,%1,%2,%3}, {%4,%5,%6,%7}, {%8,%9}, {%0,%1,%2,%3};"
        : "+f"(d[0]), "+f"(d[1]), "+f"(d[2]), "+f"(d[3])
        : "r"(a[0]), "r"(a[1]), "r"(a[2]), "r"(a[3]), "r"(b[0]), "r"(b[1]));
}
__device__ __forceinline__ void cpa16(u32 dst, const void* src) {
    asm volatile("cp.async.cg.shared.global [%0], [%1], 16;"
                 :: "r"(dst), "l"(src) : "memory");
}
__device__ __forceinline__ void cpa_commit() {
    asm volatile("cp.async.commit_group;" ::: "memory");
}
__device__ __forceinline__ void cpa_wait0() {
    asm volatile("cp.async.wait_group 0;" ::: "memory");
}
__device__ __forceinline__ void cpa_wait1() {
    asm volatile("cp.async.wait_group 1;" ::: "memory");
}
__device__ __forceinline__ u32 packh2(float a, float b) {
    __half2 h = __floats2half2_rn(a, b);
    return *reinterpret_cast<u32*>(&h);
}
__device__ __forceinline__ void bar_sync(int id, int cnt) {
    asm volatile("bar.sync %0, %1;" :: "r"(id), "r"(cnt) : "memory");
}
__device__ __forceinline__ void bar_arrive(int id, int cnt) {
    asm volatile("bar.arrive %0, %1;" :: "r"(id), "r"(cnt) : "memory");
}

// ============================================================
// Kernel 0: convert W -> g_wh (B-layout) only (x is fused into k_xw_mma)
// ============================================================
__global__ void __launch_bounds__(256) k_cvtw(const float* __restrict__ W) {
    int gid = blockIdx.x * 256 + threadIdx.x;     // 16384 total
    int k = gid >> 5;
    int c = gid & 31;
    int ktile = k >> 7, kl = k & 127;
    const float4* src = (const float4*)(W + (size_t)k * OUTF + c * 8);
    float4 a = src[0], b = src[1];
    uint4 o = make_uint4(packh2(a.x, a.y), packh2(a.z, a.w),
                         packh2(b.x, b.y), packh2(b.z, b.w));
    u32 off = (u32)ktile * 65536u + (u32)kl * 512u
            + ((((u32)c) ^ ((u32)kl & 7u)) << 4);
    *(uint4*)(g_wh + off) = o;
}

// ============================================================
// Kernel 1: h = x @ W via fp16 mma.sync; x converted IN-KERNEL.
//   Writes g_hh (fp16 swz); FUSED s1/s2 + exp tables.
// ============================================================
#define XW_SMA 0
#define XW_SMB 16384
#define XW_SMEM 147456

__global__ void __launch_bounds__(256) k_xw_mma(const float* __restrict__ x,
                                                const float* __restrict__ av) {
    extern __shared__ __align__(16) char smem[];
    const u32 sb = smem_u32(smem);
    const int tid  = threadIdx.x;
    const int lane = tid & 31;
    const int wid  = tid >> 5;
    const int wn   = wid & 3;
    const int wm   = wid >> 2;
    const int i0   = blockIdx.x * 64;

    const int oct = tid & 15;      // k-octet within tile
    const int rg  = tid >> 4;      // row group (4 rows)

    float acc[2][8][4];
    #pragma unroll
    for (int mi = 0; mi < 2; mi++)
        #pragma unroll
        for (int n8 = 0; n8 < 8; n8++)
            #pragma unroll
            for (int c = 0; c < 4; c++) acc[mi][n8][c] = 0.f;

    float4 xr[4][2];
    #define XLOAD(kt)                                                            \
    {                                                                            \
        _Pragma("unroll")                                                        \
        for (int rr = 0; rr < 4; rr++) {                                         \
            const float4* xp = (const float4*)(x + (size_t)(i0 + rg * 4 + rr) * INF_ \
                                               + (kt) * 128 + oct * 8);          \
            xr[rr][0] = xp[0]; xr[rr][1] = xp[1];                                \
        }                                                                        \
    }
    #define WISSUE(kt, bb)                                                       \
    {                                                                            \
        const u32 dstB = sb + XW_SMB + (u32)(bb) * 65536u;                       \
        const unsigned char* srcB = g_wh + (size_t)(kt) * 65536;                 \
        _Pragma("unroll")                                                        \
        for (int it = 0; it < 16; it++) {                                        \
            u32 off = (u32)tid * 16u + (u32)it * 4096u;                          \
            cpa16(dstB + off, srcB + off);                                       \
        }                                                                        \
        cpa_commit();                                                            \
    }

    XLOAD(0);
    WISSUE(0, 0);

    const u32 a_row_off = (u32)((wm * 32 + (lane & 15)) * 256);
    const u32 a_hi      = (u32)(lane >> 4);
    const u32 sxor      = (u32)(lane & 7);
    const u32 b_row_off = (u32)((lane & 15) * 512 + wn * 128);

    for (int kt = 0; kt < 4; kt++) {
        const int buf = kt & 1;
        if (kt < 3) WISSUE(kt + 1, buf ^ 1);

        // pack x regs -> A smem (fp16, swizzled), single buffer
        #pragma unroll
        for (int rr = 0; rr < 4; rr++) {
            int i = rg * 4 + rr;
            uint4 o = make_uint4(packh2(xr[rr][0].x, xr[rr][0].y),
                                 packh2(xr[rr][0].z, xr[rr][0].w),
                                 packh2(xr[rr][1].x, xr[rr][1].y),
                                 packh2(xr[rr][1].z, xr[rr][1].w));
            u32 soff = (u32)i * 256u + ((((u32)oct) ^ ((u32)i & 7u)) << 4);
            *(uint4*)(smem + XW_SMA + soff) = o;
        }
        if (kt < 3) XLOAD(kt + 1);                 // prefetch next x (hidden by MMA)
        if (kt < 3) cpa_wait1(); else cpa_wait0(); // W(kt) landed
        __syncthreads();

        const u32 Abuf = sb + XW_SMA;
        const u32 Bbuf = sb + XW_SMB + (u32)buf * 65536u;
        #pragma unroll
        for (int kk = 0; kk < 8; kk++) {
            u32 afr[2][4];
            #pragma unroll
            for (int mi = 0; mi < 2; mi++) {
                u32 chunk = (u32)(kk * 2) + a_hi;
                ldsm4(afr[mi], Abuf + a_row_off + (u32)mi * 4096u
                                  + ((chunk ^ sxor) << 4));
            }
            u32 bfr[4][4];
            #pragma unroll
            for (int nb2 = 0; nb2 < 4; nb2++) {
                u32 chunk = (u32)(nb2 * 2) + a_hi;
                ldsm4t(bfr[nb2], Bbuf + (u32)(kk * 16) * 512u + b_row_off
                                    + ((chunk ^ sxor) << 4));
            }
            #pragma unroll
            for (int mi = 0; mi < 2; mi++)
                #pragma unroll
                for (int n8 = 0; n8 < 8; n8++)
                    mma16816(acc[mi][n8], afr[mi], &bfr[n8 >> 1][(n8 & 1) * 2]);
        }
        __syncthreads();
    }

    // ---- epilogue: write g_hh fp16 swz + fused s1/s2 + exp tables ----
    const int g  = lane >> 2;
    const int tq = lane & 3;
    float* sp1 = (float*)(smem);          // [4][64]
    float* sp2 = (float*)(smem + 1024);   // [4][64]

    #pragma unroll
    for (int mi = 0; mi < 2; mi++) {
        int rl0 = wm * 32 + mi * 16 + g;
        int j0r = i0 + rl0, j8r = i0 + rl0 + 8;
        float s10 = 0.f, s20 = 0.f, s18 = 0.f, s28 = 0.f;
        #pragma unroll
        for (int n8 = 0; n8 < 8; n8++) {
            int col = wn * 64 + n8 * 8 + tq * 2;
            float2 h0 = make_float2(acc[mi][n8][0], acc[mi][n8][1]);
            float2 h8 = make_float2(acc[mi][n8][2], acc[mi][n8][3]);
            u32 off0 = (u32)j0r * 512u + ((((u32)(col >> 3)) ^ ((u32)j0r & 7u)) << 4)
                     + ((u32)(col & 7)) * 2u;
            u32 off8 = (u32)j8r * 512u + ((((u32)(col >> 3)) ^ ((u32)j8r & 7u)) << 4)
                     + ((u32)(col & 7)) * 2u;
            *(u32*)(g_hh + off0) = packh2(h0.x, h0.y);
            *(u32*)(g_hh + off8) = packh2(h8.x, h8.y);
            float2 a1v = *(const float2*)(av + col);
            float2 a2v = *(const float2*)(av + OUTF + col);
            s10 += h0.x * a1v.x + h0.y * a1v.y;
            s20 += h0.x * a2v.x + h0.y * a2v.y;
            s18 += h8.x * a1v.x + h8.y * a1v.y;
            s28 += h8.x * a2v.x + h8.y * a2v.y;
        }
        #pragma unroll
        for (int m = 1; m < 4; m <<= 1) {
            s10 += __shfl_xor_sync(0xffffffffu, s10, m);
            s20 += __shfl_xor_sync(0xffffffffu, s20, m);
            s18 += __shfl_xor_sync(0xffffffffu, s18, m);
            s28 += __shfl_xor_sync(0xffffffffu, s28, m);
        }
        if (tq == 0) {
            sp1[wn * 64 + rl0] = s10;     sp2[wn * 64 + rl0] = s20;
            sp1[wn * 64 + rl0 + 8] = s18; sp2[wn * 64 + rl0 + 8] = s28;
        }
    }
    __syncthreads();
    if (tid < 64) {
        float s1 = (sp1[tid] + sp1[64 + tid]) + (sp1[128 + tid] + sp1[192 + tid]);
        float s2 = (sp2[tid] + sp2[64 + tid]) + (sp2[128 + tid] + sp2[192 + tid]);
        int row = i0 + tid;
        g_s1[row]  = s1;
        g_s2[row]  = s2;
        g_e1p[row] = __expf(s1);
        g_e1n[row] = __expf(ALPHA * s1);
        g_e2p[row] = __expf(s2);
        g_e2n[row] = __expf(ALPHA * s2);
    }
    #undef XLOAD
    #undef WISSUE
}

// ============================================================
// Kernel 3: warp-specialized fused masked-softmax + P@h
//   Consumers IDENTICAL to R9/R13. Producer defers B-completion wait
//   by one tile (wait_group 1 covers B(t-1); B(t) stays in flight).
// ============================================================
#define KT 128
#define NTILE (NN / KT)
#define SM_ZP   0
#define SM_A    4096
#define SM_B    36864
#define SMEM_ATTN 167936
#define NTHREADS 512

__global__ void __launch_bounds__(NTHREADS) k_attn(const int* __restrict__ adj,
                                                   const float* __restrict__ bias,
                                                   float* __restrict__ out) {
    extern __shared__ __align__(16) char smem[];
    const u32 sb = smem_u32(smem);
    const int tid  = threadIdx.x;
    const int lane = tid & 31;
    const int wid  = tid >> 5;
    const int i0   = blockIdx.x * 64;
    float* zp = (float*)(smem + SM_ZP);    // zp[16][64]

    if (wid < 8) {
        // ================= CONSUMERS: MMA (unchanged) =================
        const int wn = wid & 3;
        const int wm = wid >> 2;

        float acc[2][8][4];
        #pragma unroll
        for (int mi = 0; mi < 2; mi++)
            #pragma unroll
            for (int n8 = 0; n8 < 8; n8++)
                #pragma unroll
                for (int c = 0; c < 4; c++) acc[mi][n8][c] = 0.f;

        const u32 a_row_off = (u32)((wm * 32 + (lane & 15)) * 256);
        const u32 a_hi      = (u32)(lane >> 4);
        const u32 sxor      = (u32)(lane & 7);
        const u32 b_row_off = (u32)((lane & 15) * 512 + wn * 128);

        for (int t = 0; t < NTILE; t++) {
            const int p = t & 1;
            bar_sync(1 + p, NTHREADS);   // wait full[p]

            const u32 Abuf = sb + SM_A + (u32)p * 16384u;
            const u32 Bbuf = sb + SM_B + (u32)p * 65536u;
            #pragma unroll
            for (int kk = 0; kk < 8; kk++) {
                u32 afr[2][4];
                #pragma unroll
                for (int mi = 0; mi < 2; mi++) {
                    u32 chunk = (u32)(kk * 2) + a_hi;
                    ldsm4(afr[mi], Abuf + a_row_off + (u32)mi * 4096u
                                      + ((chunk ^ sxor) << 4));
                }
                u32 bfr[4][4];
                #pragma unroll
                for (int nb2 = 0; nb2 < 4; nb2++) {
                    u32 chunk = (u32)(nb2 * 2) + a_hi;
                    ldsm4t(bfr[nb2], Bbuf + (u32)(kk * 16) * 512u + b_row_off
                                        + ((chunk ^ sxor) << 4));
                }
                #pragma unroll
                for (int mi = 0; mi < 2; mi++)
                    #pragma unroll
                    for (int n8 = 0; n8 < 8; n8++)
                        mma16816(acc[mi][n8], afr[mi], &bfr[n8 >> 1][(n8 & 1) * 2]);
            }
            bar_arrive(3 + p, NTHREADS); // signal empty[p]
        }

        __syncthreads();   // producers have written zp

        // ---- epilogue: out = acc/Z + bias ----
        const int g  = lane >> 2;
        const int tq = lane & 3;
        #pragma unroll
        for (int mi = 0; mi < 2; mi++) {
            int rl0 = wm * 32 + mi * 16 + g;
            float z0 = 0.f, z8 = 0.f;
            #pragma unroll
            for (int o = 0; o < 16; o++) {
                z0 += zp[o * 64 + rl0];
                z8 += zp[o * 64 + rl0 + 8];
            }
            float inv0 = (z0 > 0.f) ? 1.0f / z0 : 0.f;
            float inv8 = (z8 > 0.f) ? 1.0f / z8 : 0.f;
            float* o0 = out + (size_t)(i0 + rl0) * OUTF;
            float* o8 = out + (size_t)(i0 + rl0 + 8) * OUTF;
            #pragma unroll
            for (int n8 = 0; n8 < 8; n8++) {
                int col = wn * 64 + n8 * 8 + tq * 2;
                float2 b2 = *(const float2*)(bias + col);
                float2 r0, r8;
                r0.x = acc[mi][n8][0] * inv0 + b2.x;
                r0.y = acc[mi][n8][1] * inv0 + b2.y;
                r8.x = acc[mi][n8][2] * inv8 + b2.x;
                r8.y = acc[mi][n8][3] * inv8 + b2.y;
                *(float2*)(o0 + col) = r0;
                *(float2*)(o8 + col) = r8;
            }
        }
    } else {
        // ========= PRODUCERS: adj + pack A + B cp.async (deferred wait) =========
        const int ptid = tid - 256;        // 0..255
        const int oct  = ptid & 15;        // j-octet: j = oct*8 .. +7
        const int rg   = ptid >> 4;        // 0..15 -> rows rg*4 .. +3
        float s1v[4], e1pv[4], e1nv[4], zacc[4];
        #pragma unroll
        for (int rr = 0; rr < 4; rr++) {
            int i = rg * 4 + rr;
            s1v[rr]  = g_s1[i0 + i];
            e1pv[rr] = g_e1p[i0 + i];
            e1nv[rr] = g_e1n[i0 + i];
            zacc[rr] = 0.f;
        }

        for (int tp = 0; tp < NTILE; tp++) {
            const int p = tp & 1;
            if (tp >= 2) bar_sync(3 + p, NTHREADS);   // wait empty[p]

            // ---- issue B(tp) cp.async (64KB pre-swizzled fp16 h) ----
            {
                const u32 dstB = sb + SM_B + (u32)p * 65536u;
                const unsigned char* src = g_hh + (size_t)tp * 65536 + ptid * 16;
                #pragma unroll
                for (int it = 0; it < 16; it++)
                    cpa16(dstB + (u32)ptid * 16u + (u32)it * 4096u, src + it * 4096);
                cpa_commit();
            }

            // ---- pack P tile tp: 4 rows x 8 j per thread ----
            {
                const int jb = tp * KT + oct * 8;
                float4 s2a = *(const float4*)(g_s2  + jb);
                float4 s2b = *(const float4*)(g_s2  + jb + 4);
                float4 epa = *(const float4*)(g_e2p + jb);
                float4 epb = *(const float4*)(g_e2p + jb + 4);
                float4 ena = *(const float4*)(g_e2n + jb);
                float4 enb = *(const float4*)(g_e2n + jb + 4);
                char* Ah = smem + SM_A + p * 16384;
                #pragma unroll
                for (int rr = 0; rr < 4; rr++) {
                    int i = rg * 4 + rr;
                    const int* ar = adj + (size_t)(i0 + i) * NN + jb;
                    int4 a0 = *(const int4*)ar;
                    int4 a1 = *(const int4*)(ar + 4);
                    float s1 = s1v[rr], ep = e1pv[rr], en = e1nv[rr];
                    float p0 = (a0.x > 0) ? ((s1 + s2a.x > 0.f) ? ep * epa.x : en * ena.x) : 0.f;
                    float p1 = (a0.y > 0) ? ((s1 + s2a.y > 0.f) ? ep * epa.y : en * ena.y) : 0.f;
                    float p2 = (a0.z > 0) ? ((s1 + s2a.z > 0.f) ? ep * epa.z : en * ena.z) : 0.f;
                    float p3 = (a0.w > 0) ? ((s1 + s2a.w > 0.f) ? ep * epa.w : en * ena.w) : 0.f;
                    float p4 = (a1.x > 0) ? ((s1 + s2b.x > 0.f) ? ep * epb.x : en * enb.x) : 0.f;
                    float p5 = (a1.y > 0) ? ((s1 + s2b.y > 0.f) ? ep * epb.y : en * enb.y) : 0.f;
                    float p6 = (a1.z > 0) ? ((s1 + s2b.z > 0.f) ? ep * epb.z : en * enb.z) : 0.f;
                    float p7 = (a1.w > 0) ? ((s1 + s2b.w > 0.f) ? ep * epb.w : en * enb.w) : 0.f;
                    zacc[rr] += ((p0 + p1) + (p2 + p3)) + ((p4 + p5) + (p6 + p7));
                    uint4 o = make_uint4(packh2(p0, p1), packh2(p2, p3),
                                         packh2(p4, p5), packh2(p6, p7));
                    u32 soff = (u32)i * 256u + ((((u32)oct) ^ ((u32)i & 7u)) << 4);
                    *(uint4*)(Ah + soff) = o;
                }
            }

            // ---- deferred completion: B(tp-1) done (B(tp) still in flight) ----
            if (tp > 0) {
                cpa_wait1();
                bar_arrive(1 + ((tp - 1) & 1), NTHREADS);  // full[tp-1]
            }
        }
        // epilogue: last tile
        cpa_wait0();
        bar_arrive(1 + ((NTILE - 1) & 1), NTHREADS);       // full[NTILE-1]

        #pragma unroll
        for (int rr = 0; rr < 4; rr++)
            zp[oct * 64 + rg * 4 + rr] = zacc[rr];
        __syncthreads();
    }
}

// ============================================================
extern "C" void kernel_launch(void* const* d_in, const int* in_sizes, int n_in,
                              void* d_out, int out_size) {
    (void)in_sizes; (void)n_in; (void)out_size;
    const float* x    = (const float*)d_in[0];
    const int*   adj  = (const int*)  d_in[1];
    const float* W    = (const float*)d_in[2];
    const float* a    = (const float*)d_in[3];
    const float* bias = (const float*)d_in[4];
    float* out = (float*)d_out;

    cudaFuncSetAttribute(k_xw_mma, cudaFuncAttributeMaxDynamicSharedMemorySize, XW_SMEM);
    cudaFuncSetAttribute(k_attn,   cudaFuncAttributeMaxDynamicSharedMemorySize, SMEM_ATTN);

    k_cvtw  <<<64, 256>>>(W);
    k_xw_mma<<<NN / 64, 256, XW_SMEM>>>(x, a);
    k_attn  <<<NN / 64, NTHREADS, SMEM_ATTN>>>(adj, bias, out);
}

// round 15
// speedup vs baseline: 1.3365x; 1.3365x over previous
#include <cuda_runtime.h>
#include <cuda_fp16.h>
#include <cstdint>
#include <cstddef>

#define NN    8192
#define INF_  512
#define OUTF  256
#define ALPHA 0.2f

typedef unsigned long long u64;
typedef unsigned int u32;

// ---------------- scratch globals (no allocs allowed) ----------------
__device__ float g_s1[NN];
__device__ float g_s2[NN];
__device__ float g_e1p[NN];   // exp(s1)
__device__ float g_e1n[NN];   // exp(ALPHA*s1)
__device__ float g_e2p[NN];   // exp(s2)
__device__ float g_e2n[NN];   // exp(ALPHA*s2)
// h as fp16, PRE-SWIZZLED B-layout: byte(j,n) = j*512 + (((n>>3)^(j&7))<<4) + (n&7)*2
__device__ __align__(16) unsigned char g_hh[(size_t)NN * 512];
// W as fp16, PRE-SWIZZLED B-layout per 128-k tile
__device__ __align__(16) unsigned char g_wh[(size_t)INF_ * 512];

// ---------------- mma / ldmatrix / cp.async / barrier helpers ----------------
__device__ __forceinline__ u32 smem_u32(const void* p) {
    u32 a;
    asm("{ .reg .u64 t; cvta.to.shared.u64 t, %1; cvt.u32.u64 %0, t; }"
        : "=r"(a) : "l"(p));
    return a;
}
__device__ __forceinline__ void ldsm4(u32* r, u32 addr) {
    asm volatile("ldmatrix.sync.aligned.m8n8.x4.shared.b16 {%0,%1,%2,%3}, [%4];"
                 : "=r"(r[0]), "=r"(r[1]), "=r"(r[2]), "=r"(r[3]) : "r"(addr));
}
__device__ __forceinline__ void ldsm4t(u32* r, u32 addr) {
    asm volatile("ldmatrix.sync.aligned.m8n8.x4.trans.shared.b16 {%0,%1,%2,%3}, [%4];"
                 : "=r"(r[0]), "=r"(r[1]), "=r"(r[2]), "=r"(r[3]) : "r"(addr));
}
__device__ __forceinline__ void mma16816(float* d, const u32* a, const u32* b) {
    asm volatile(
        "mma.sync.aligned.m16n8k16.row.col.f32.f16.f16.f32 "
        "{%0,%1,%2,%3}, {%4,%5,%6,%7}, {%8,%9}, {%0,%1,%2,%3};"
        : "+f"(d[0]), "+f"(d[1]), "+f"(d[2]), "+f"(d[3])
        : "r"(a[0]), "r"(a[1]), "r"(a[2]), "r"(a[3]), "r"(b[0]), "r"(b[1]));
}
__device__ __forceinline__ void cpa16(u32 dst, const void* src) {
    asm volatile("cp.async.cg.shared.global [%0], [%1], 16;"
                 :: "r"(dst), "l"(src) : "memory");
}
__device__ __forceinline__ void cpa_commit() {
    asm volatile("cp.async.commit_group;" ::: "memory");
}
__device__ __forceinline__ void cpa_wait0() {
    asm volatile("cp.async.wait_group 0;" ::: "memory");
}
__device__ __forceinline__ void cpa_wait1() {
    asm volatile("cp.async.wait_group 1;" ::: "memory");
}
__device__ __forceinline__ u32 packh2(float a, float b) {
    __half2 h = __floats2half2_rn(a, b);
    return *reinterpret_cast<u32*>(&h);
}
__device__ __forceinline__ void bar_sync(int id, int cnt) {
    asm volatile("bar.sync %0, %1;" :: "r"(id), "r"(cnt) : "memory");
}
__device__ __forceinline__ void bar_arrive(int id, int cnt) {
    asm volatile("bar.arrive %0, %1;" :: "r"(id), "r"(cnt) : "memory");
}

// ============================================================
// Kernel 0: convert W -> g_wh (B-layout) only (x fused into k_xw_mma)
// ============================================================
__global__ void __launch_bounds__(256) k_cvtw(const float* __restrict__ W) {
    int gid = blockIdx.x * 256 + threadIdx.x;     // 16384 total
    int k = gid >> 5;
    int c = gid & 31;
    int ktile = k >> 7, kl = k & 127;
    const float4* src = (const float4*)(W + (size_t)k * OUTF + c * 8);
    float4 a = src[0], b = src[1];
    uint4 o = make_uint4(packh2(a.x, a.y), packh2(a.z, a.w),
                         packh2(b.x, b.y), packh2(b.z, b.w));
    u32 off = (u32)ktile * 65536u + (u32)kl * 512u
            + ((((u32)c) ^ ((u32)kl & 7u)) << 4);
    *(uint4*)(g_wh + off) = o;
}

// ============================================================
// Kernel 1: h = x @ W via fp16 mma.sync; x converted IN-KERNEL.
//   Writes g_hh (fp16 swz); FUSED s1/s2 + exp tables. (R14 version,
//   correctness-proven; independent of k_attn.)
// ============================================================
#define XW_SMA 0
#define XW_SMB 16384
#define XW_SMEM 147456

__global__ void __launch_bounds__(256) k_xw_mma(const float* __restrict__ x,
                                                const float* __restrict__ av) {
    extern __shared__ __align__(16) char smem[];
    const u32 sb = smem_u32(smem);
    const int tid  = threadIdx.x;
    const int lane = tid & 31;
    const int wid  = tid >> 5;
    const int wn   = wid & 3;
    const int wm   = wid >> 2;
    const int i0   = blockIdx.x * 64;

    const int oct = tid & 15;      // k-octet within tile
    const int rg  = tid >> 4;      // row group (4 rows)

    float acc[2][8][4];
    #pragma unroll
    for (int mi = 0; mi < 2; mi++)
        #pragma unroll
        for (int n8 = 0; n8 < 8; n8++)
            #pragma unroll
            for (int c = 0; c < 4; c++) acc[mi][n8][c] = 0.f;

    float4 xr[4][2];
    #define XLOAD(kt)                                                            \
    {                                                                            \
        _Pragma("unroll")                                                        \
        for (int rr = 0; rr < 4; rr++) {                                         \
            const float4* xp = (const float4*)(x + (size_t)(i0 + rg * 4 + rr) * INF_ \
                                               + (kt) * 128 + oct * 8);          \
            xr[rr][0] = xp[0]; xr[rr][1] = xp[1];                                \
        }                                                                        \
    }
    #define WISSUE(kt, bb)                                                       \
    {                                                                            \
        const u32 dstB = sb + XW_SMB + (u32)(bb) * 65536u;                       \
        const unsigned char* srcB = g_wh + (size_t)(kt) * 65536;                 \
        _Pragma("unroll")                                                        \
        for (int it = 0; it < 16; it++) {                                        \
            u32 off = (u32)tid * 16u + (u32)it * 4096u;                          \
            cpa16(dstB + off, srcB + off);                                       \
        }                                                                        \
        cpa_commit();                                                            \
    }

    XLOAD(0);
    WISSUE(0, 0);

    const u32 a_row_off = (u32)((wm * 32 + (lane & 15)) * 256);
    const u32 a_hi      = (u32)(lane >> 4);
    const u32 sxor      = (u32)(lane & 7);
    const u32 b_row_off = (u32)((lane & 15) * 512 + wn * 128);

    for (int kt = 0; kt < 4; kt++) {
        const int buf = kt & 1;
        if (kt < 3) WISSUE(kt + 1, buf ^ 1);

        // pack x regs -> A smem (fp16, swizzled), single buffer
        #pragma unroll
        for (int rr = 0; rr < 4; rr++) {
            int i = rg * 4 + rr;
            uint4 o = make_uint4(packh2(xr[rr][0].x, xr[rr][0].y),
                                 packh2(xr[rr][0].z, xr[rr][0].w),
                                 packh2(xr[rr][1].x, xr[rr][1].y),
                                 packh2(xr[rr][1].z, xr[rr][1].w));
            u32 soff = (u32)i * 256u + ((((u32)oct) ^ ((u32)i & 7u)) << 4);
            *(uint4*)(smem + XW_SMA + soff) = o;
        }
        if (kt < 3) XLOAD(kt + 1);                 // prefetch next x (hidden by MMA)
        if (kt < 3) cpa_wait1(); else cpa_wait0(); // W(kt) landed
        __syncthreads();

        const u32 Abuf = sb + XW_SMA;
        const u32 Bbuf = sb + XW_SMB + (u32)buf * 65536u;
        #pragma unroll
        for (int kk = 0; kk < 8; kk++) {
            u32 afr[2][4];
            #pragma unroll
            for (int mi = 0; mi < 2; mi++) {
                u32 chunk = (u32)(kk * 2) + a_hi;
                ldsm4(afr[mi], Abuf + a_row_off + (u32)mi * 4096u
                                  + ((chunk ^ sxor) << 4));
            }
            u32 bfr[4][4];
            #pragma unroll
            for (int nb2 = 0; nb2 < 4; nb2++) {
                u32 chunk = (u32)(nb2 * 2) + a_hi;
                ldsm4t(bfr[nb2], Bbuf + (u32)(kk * 16) * 512u + b_row_off
                                    + ((chunk ^ sxor) << 4));
            }
            #pragma unroll
            for (int mi = 0; mi < 2; mi++)
                #pragma unroll
                for (int n8 = 0; n8 < 8; n8++)
                    mma16816(acc[mi][n8], afr[mi], &bfr[n8 >> 1][(n8 & 1) * 2]);
        }
        __syncthreads();
    }

    // ---- epilogue: write g_hh fp16 swz + fused s1/s2 + exp tables ----
    const int g  = lane >> 2;
    const int tq = lane & 3;
    float* sp1 = (float*)(smem);          // [4][64]
    float* sp2 = (float*)(smem + 1024);   // [4][64]

    #pragma unroll
    for (int mi = 0; mi < 2; mi++) {
        int rl0 = wm * 32 + mi * 16 + g;
        int j0r = i0 + rl0, j8r = i0 + rl0 + 8;
        float s10 = 0.f, s20 = 0.f, s18 = 0.f, s28 = 0.f;
        #pragma unroll
        for (int n8 = 0; n8 < 8; n8++) {
            int col = wn * 64 + n8 * 8 + tq * 2;
            float2 h0 = make_float2(acc[mi][n8][0], acc[mi][n8][1]);
            float2 h8 = make_float2(acc[mi][n8][2], acc[mi][n8][3]);
            u32 off0 = (u32)j0r * 512u + ((((u32)(col >> 3)) ^ ((u32)j0r & 7u)) << 4)
                     + ((u32)(col & 7)) * 2u;
            u32 off8 = (u32)j8r * 512u + ((((u32)(col >> 3)) ^ ((u32)j8r & 7u)) << 4)
                     + ((u32)(col & 7)) * 2u;
            *(u32*)(g_hh + off0) = packh2(h0.x, h0.y);
            *(u32*)(g_hh + off8) = packh2(h8.x, h8.y);
            float2 a1v = *(const float2*)(av + col);
            float2 a2v = *(const float2*)(av + OUTF + col);
            s10 += h0.x * a1v.x + h0.y * a1v.y;
            s20 += h0.x * a2v.x + h0.y * a2v.y;
            s18 += h8.x * a1v.x + h8.y * a1v.y;
            s28 += h8.x * a2v.x + h8.y * a2v.y;
        }
        #pragma unroll
        for (int m = 1; m < 4; m <<= 1) {
            s10 += __shfl_xor_sync(0xffffffffu, s10, m);
            s20 += __shfl_xor_sync(0xffffffffu, s20, m);
            s18 += __shfl_xor_sync(0xffffffffu, s18, m);
            s28 += __shfl_xor_sync(0xffffffffu, s28, m);
        }
        if (tq == 0) {
            sp1[wn * 64 + rl0] = s10;     sp2[wn * 64 + rl0] = s20;
            sp1[wn * 64 + rl0 + 8] = s18; sp2[wn * 64 + rl0 + 8] = s28;
        }
    }
    __syncthreads();
    if (tid < 64) {
        float s1 = (sp1[tid] + sp1[64 + tid]) + (sp1[128 + tid] + sp1[192 + tid]);
        float s2 = (sp2[tid] + sp2[64 + tid]) + (sp2[128 + tid] + sp2[192 + tid]);
        int row = i0 + tid;
        g_s1[row]  = s1;
        g_s2[row]  = s2;
        g_e1p[row] = __expf(s1);
        g_e1n[row] = __expf(ALPHA * s1);
        g_e2p[row] = __expf(s2);
        g_e2n[row] = __expf(ALPHA * s2);
    }
    #undef XLOAD
    #undef WISSUE
}

// ============================================================
// Kernel 3: warp-specialized fused masked-softmax + P@h  (R9/R13 VERBATIM)
//   512 threads: warps 0-7 consumers (MMA), warps 8-15 producers.
//   Producer: issue B(tp) -> pack A(tp) -> wait_group 0 -> arrive full[tp].
// ============================================================
#define KT 128
#define NTILE (NN / KT)
#define SM_ZP   0
#define SM_A    4096
#define SM_B    36864
#define SMEM_ATTN 167936
#define NTHREADS 512

__global__ void __launch_bounds__(NTHREADS) k_attn(const int* __restrict__ adj,
                                                   const float* __restrict__ bias,
                                                   float* __restrict__ out) {
    extern __shared__ __align__(16) char smem[];
    const u32 sb = smem_u32(smem);
    const int tid  = threadIdx.x;
    const int lane = tid & 31;
    const int wid  = tid >> 5;
    const int i0   = blockIdx.x * 64;
    float* zp = (float*)(smem + SM_ZP);    // zp[16][64]

    if (wid < 8) {
        // ================= CONSUMERS: MMA =================
        const int wn = wid & 3;
        const int wm = wid >> 2;

        float acc[2][8][4];
        #pragma unroll
        for (int mi = 0; mi < 2; mi++)
            #pragma unroll
            for (int n8 = 0; n8 < 8; n8++)
                #pragma unroll
                for (int c = 0; c < 4; c++) acc[mi][n8][c] = 0.f;

        const u32 a_row_off = (u32)((wm * 32 + (lane & 15)) * 256);
        const u32 a_hi      = (u32)(lane >> 4);
        const u32 sxor      = (u32)(lane & 7);
        const u32 b_row_off = (u32)((lane & 15) * 512 + wn * 128);

        for (int t = 0; t < NTILE; t++) {
            const int p = t & 1;
            bar_sync(1 + p, NTHREADS);   // wait full[p]

            const u32 Abuf = sb + SM_A + (u32)p * 16384u;
            const u32 Bbuf = sb + SM_B + (u32)p * 65536u;
            #pragma unroll
            for (int kk = 0; kk < 8; kk++) {
                u32 afr[2][4];
                #pragma unroll
                for (int mi = 0; mi < 2; mi++) {
                    u32 chunk = (u32)(kk * 2) + a_hi;
                    ldsm4(afr[mi], Abuf + a_row_off + (u32)mi * 4096u
                                      + ((chunk ^ sxor) << 4));
                }
                u32 bfr[4][4];
                #pragma unroll
                for (int nb2 = 0; nb2 < 4; nb2++) {
                    u32 chunk = (u32)(nb2 * 2) + a_hi;
                    ldsm4t(bfr[nb2], Bbuf + (u32)(kk * 16) * 512u + b_row_off
                                        + ((chunk ^ sxor) << 4));
                }
                #pragma unroll
                for (int mi = 0; mi < 2; mi++)
                    #pragma unroll
                    for (int n8 = 0; n8 < 8; n8++)
                        mma16816(acc[mi][n8], afr[mi], &bfr[n8 >> 1][(n8 & 1) * 2]);
            }
            bar_arrive(3 + p, NTHREADS); // signal empty[p]
        }

        __syncthreads();   // producers have written zp

        // ---- epilogue: out = acc/Z + bias ----
        const int g  = lane >> 2;
        const int tq = lane & 3;
        #pragma unroll
        for (int mi = 0; mi < 2; mi++) {
            int rl0 = wm * 32 + mi * 16 + g;
            float z0 = 0.f, z8 = 0.f;
            #pragma unroll
            for (int o = 0; o < 16; o++) {
                z0 += zp[o * 64 + rl0];
                z8 += zp[o * 64 + rl0 + 8];
            }
            float inv0 = (z0 > 0.f) ? 1.0f / z0 : 0.f;
            float inv8 = (z8 > 0.f) ? 1.0f / z8 : 0.f;
            float* o0 = out + (size_t)(i0 + rl0) * OUTF;
            float* o8 = out + (size_t)(i0 + rl0 + 8) * OUTF;
            #pragma unroll
            for (int n8 = 0; n8 < 8; n8++) {
                int col = wn * 64 + n8 * 8 + tq * 2;
                float2 b2 = *(const float2*)(bias + col);
                float2 r0, r8;
                r0.x = acc[mi][n8][0] * inv0 + b2.x;
                r0.y = acc[mi][n8][1] * inv0 + b2.y;
                r8.x = acc[mi][n8][2] * inv8 + b2.x;
                r8.y = acc[mi][n8][3] * inv8 + b2.y;
                *(float2*)(o0 + col) = r0;
                *(float2*)(o8 + col) = r8;
            }
        }
    } else {
        // ================= PRODUCERS: adj + pack A + B cp.async =================
        const int ptid = tid - 256;        // 0..255
        const int oct  = ptid & 15;        // j-octet: j = oct*8 .. +7
        const int rg   = ptid >> 4;        // 0..15 -> rows rg*4 .. +3
        float s1v[4], e1pv[4], e1nv[4], zacc[4];
        #pragma unroll
        for (int rr = 0; rr < 4; rr++) {
            int i = rg * 4 + rr;
            s1v[rr]  = g_s1[i0 + i];
            e1pv[rr] = g_e1p[i0 + i];
            e1nv[rr] = g_e1n[i0 + i];
            zacc[rr] = 0.f;
        }

        for (int tp = 0; tp < NTILE; tp++) {
            const int p = tp & 1;
            if (tp >= 2) bar_sync(3 + p, NTHREADS);   // wait empty[p]

            // ---- issue B cp.async (64KB pre-swizzled fp16 h) ----
            {
                const u32 dstB = sb + SM_B + (u32)p * 65536u;
                const unsigned char* src = g_hh + (size_t)tp * 65536 + ptid * 16;
                #pragma unroll
                for (int it = 0; it < 16; it++)
                    cpa16(dstB + (u32)ptid * 16u + (u32)it * 4096u, src + it * 4096);
                cpa_commit();
            }

            // ---- pack P tile: 4 rows x 8 j per thread ----
            {
                const int jb = tp * KT + oct * 8;
                float4 s2a = *(const float4*)(g_s2  + jb);
                float4 s2b = *(const float4*)(g_s2  + jb + 4);
                float4 epa = *(const float4*)(g_e2p + jb);
                float4 epb = *(const float4*)(g_e2p + jb + 4);
                float4 ena = *(const float4*)(g_e2n + jb);
                float4 enb = *(const float4*)(g_e2n + jb + 4);
                char* Ah = smem + SM_A + p * 16384;
                #pragma unroll
                for (int rr = 0; rr < 4; rr++) {
                    int i = rg * 4 + rr;
                    const int* ar = adj + (size_t)(i0 + i) * NN + jb;
                    int4 a0 = *(const int4*)ar;
                    int4 a1 = *(const int4*)(ar + 4);
                    float s1 = s1v[rr], ep = e1pv[rr], en = e1nv[rr];
                    float p0 = (a0.x > 0) ? ((s1 + s2a.x > 0.f) ? ep * epa.x : en * ena.x) : 0.f;
                    float p1 = (a0.y > 0) ? ((s1 + s2a.y > 0.f) ? ep * epa.y : en * ena.y) : 0.f;
                    float p2 = (a0.z > 0) ? ((s1 + s2a.z > 0.f) ? ep * epa.z : en * ena.z) : 0.f;
                    float p3 = (a0.w > 0) ? ((s1 + s2a.w > 0.f) ? ep * epa.w : en * ena.w) : 0.f;
                    float p4 = (a1.x > 0) ? ((s1 + s2b.x > 0.f) ? ep * epb.x : en * enb.x) : 0.f;
                    float p5 = (a1.y > 0) ? ((s1 + s2b.y > 0.f) ? ep * epb.y : en * enb.y) : 0.f;
                    float p6 = (a1.z > 0) ? ((s1 + s2b.z > 0.f) ? ep * epb.z : en * enb.z) : 0.f;
                    float p7 = (a1.w > 0) ? ((s1 + s2b.w > 0.f) ? ep * epb.w : en * enb.w) : 0.f;
                    zacc[rr] += ((p0 + p1) + (p2 + p3)) + ((p4 + p5) + (p6 + p7));
                    uint4 o = make_uint4(packh2(p0, p1), packh2(p2, p3),
                                         packh2(p4, p5), packh2(p6, p7));
                    u32 soff = (u32)i * 256u + ((((u32)oct) ^ ((u32)i & 7u)) << 4);
                    *(uint4*)(Ah + soff) = o;
                }
            }

            cpa_wait0();                  // B[p] landed
            bar_arrive(1 + p, NTHREADS);  // signal full[p]
        }

        #pragma unroll
        for (int rr = 0; rr < 4; rr++)
            zp[oct * 64 + rg * 4 + rr] = zacc[rr];
        __syncthreads();
    }
}

// ============================================================
extern "C" void kernel_launch(void* const* d_in, const int* in_sizes, int n_in,
                              void* d_out, int out_size) {
    (void)in_sizes; (void)n_in; (void)out_size;
    const float* x    = (const float*)d_in[0];
    const int*   adj  = (const int*)  d_in[1];
    const float* W    = (const float*)d_in[2];
    const float* a    = (const float*)d_in[3];
    const float* bias = (const float*)d_in[4];
    float* out = (float*)d_out;

    cudaFuncSetAttribute(k_xw_mma, cudaFuncAttributeMaxDynamicSharedMemorySize, XW_SMEM);
    cudaFuncSetAttribute(k_attn,   cudaFuncAttributeMaxDynamicSharedMemorySize, SMEM_ATTN);

    k_cvtw  <<<64, 256>>>(W);
    k_xw_mma<<<NN / 64, 256, XW_SMEM>>>(x, a);
    k_attn  <<<NN / 64, NTHREADS, SMEM_ATTN>>>(adj, bias, out);
}

// round 16
// speedup vs baseline: 1.3435x; 1.0053x over previous
#include <cuda_runtime.h>
#include <cuda_fp16.h>
#include <cstdint>
#include <cstddef>

#define NN    8192
#define INF_  512
#define OUTF  256
#define ALPHA 0.2f

typedef unsigned long long u64;
typedef unsigned int u32;

// ---------------- scratch globals (no allocs allowed) ----------------
__device__ float g_s1[NN];
__device__ float g_s2[NN];
__device__ float g_e1p[NN];   // exp(s1)
__device__ float g_e1n[NN];   // exp(ALPHA*s1)
__device__ float g_e2p[NN];   // exp(s2)
__device__ float g_e2n[NN];   // exp(ALPHA*s2)
// h as fp16, PRE-SWIZZLED B-layout: byte(j,n) = j*512 + (((n>>3)^(j&7))<<4) + (n&7)*2
__device__ __align__(16) unsigned char g_hh[(size_t)NN * 512];
// W as fp16, PRE-SWIZZLED B-layout per 128-k tile
__device__ __align__(16) unsigned char g_wh[(size_t)INF_ * 512];

// ---------------- mma / ldmatrix / cp.async / barrier helpers ----------------
__device__ __forceinline__ u32 smem_u32(const void* p) {
    u32 a;
    asm("{ .reg .u64 t; cvta.to.shared.u64 t, %1; cvt.u32.u64 %0, t; }"
        : "=r"(a) : "l"(p));
    return a;
}
__device__ __forceinline__ void ldsm4(u32* r, u32 addr) {
    asm volatile("ldmatrix.sync.aligned.m8n8.x4.shared.b16 {%0,%1,%2,%3}, [%4];"
                 : "=r"(r[0]), "=r"(r[1]), "=r"(r[2]), "=r"(r[3]) : "r"(addr));
}
__device__ __forceinline__ void ldsm4t(u32* r, u32 addr) {
    asm volatile("ldmatrix.sync.aligned.m8n8.x4.trans.shared.b16 {%0,%1,%2,%3}, [%4];"
                 : "=r"(r[0]), "=r"(r[1]), "=r"(r[2]), "=r"(r[3]) : "r"(addr));
}
__device__ __forceinline__ void mma16816(float* d, const u32* a, const u32* b) {
    asm volatile(
        "mma.sync.aligned.m16n8k16.row.col.f32.f16.f16.f32 "
        "{%0,%1,%2,%3}, {%4,%5,%6,%7}, {%8,%9}, {%0,%1,%2,%3};"
        : "+f"(d[0]), "+f"(d[1]), "+f"(d[2]), "+f"(d[3])
        : "r"(a[0]), "r"(a[1]), "r"(a[2]), "r"(a[3]), "r"(b[0]), "r"(b[1]));
}
__device__ __forceinline__ void cpa16(u32 dst, const void* src) {
    asm volatile("cp.async.cg.shared.global [%0], [%1], 16;"
                 :: "r"(dst), "l"(src) : "memory");
}
__device__ __forceinline__ void cpa_commit() {
    asm volatile("cp.async.commit_group;" ::: "memory");
}
__device__ __forceinline__ void cpa_wait0() {
    asm volatile("cp.async.wait_group 0;" ::: "memory");
}
__device__ __forceinline__ void cpa_wait1() {
    asm volatile("cp.async.wait_group 1;" ::: "memory");
}
__device__ __forceinline__ u32 packh2(float a, float b) {
    __half2 h = __floats2half2_rn(a, b);
    return *reinterpret_cast<u32*>(&h);
}
__device__ __forceinline__ void bar_sync(int id, int cnt) {
    asm volatile("bar.sync %0, %1;" :: "r"(id), "r"(cnt) : "memory");
}
__device__ __forceinline__ void bar_arrive(int id, int cnt) {
    asm volatile("bar.arrive %0, %1;" :: "r"(id), "r"(cnt) : "memory");
}

// ============================================================
// Kernel 0: convert W -> g_wh (B-layout) only (x fused into k_xw_mma)
// ============================================================
__global__ void __launch_bounds__(256) k_cvtw(const float* __restrict__ W) {
    int gid = blockIdx.x * 256 + threadIdx.x;     // 16384 total
    int k = gid >> 5;
    int c = gid & 31;
    int ktile = k >> 7, kl = k & 127;
    const float4* src = (const float4*)(W + (size_t)k * OUTF + c * 8);
    float4 a = src[0], b = src[1];
    uint4 o = make_uint4(packh2(a.x, a.y), packh2(a.z, a.w),
                         packh2(b.x, b.y), packh2(b.z, b.w));
    u32 off = (u32)ktile * 65536u + (u32)kl * 512u
            + ((((u32)c) ^ ((u32)kl & 7u)) << 4);
    *(uint4*)(g_wh + off) = o;
}

// ============================================================
// Kernel 1: h = x @ W via fp16 mma.sync; x converted IN-KERNEL.
//   Writes g_hh (fp16 swz); FUSED s1/s2 + exp tables. (R15 verbatim)
// ============================================================
#define XW_SMA 0
#define XW_SMB 16384
#define XW_SMEM 147456

__global__ void __launch_bounds__(256) k_xw_mma(const float* __restrict__ x,
                                                const float* __restrict__ av) {
    extern __shared__ __align__(16) char smem[];
    const u32 sb = smem_u32(smem);
    const int tid  = threadIdx.x;
    const int lane = tid & 31;
    const int wid  = tid >> 5;
    const int wn   = wid & 3;
    const int wm   = wid >> 2;
    const int i0   = blockIdx.x * 64;

    const int oct = tid & 15;      // k-octet within tile
    const int rg  = tid >> 4;      // row group (4 rows)

    float acc[2][8][4];
    #pragma unroll
    for (int mi = 0; mi < 2; mi++)
        #pragma unroll
        for (int n8 = 0; n8 < 8; n8++)
            #pragma unroll
            for (int c = 0; c < 4; c++) acc[mi][n8][c] = 0.f;

    float4 xr[4][2];
    #define XLOAD(kt)                                                            \
    {                                                                            \
        _Pragma("unroll")                                                        \
        for (int rr = 0; rr < 4; rr++) {                                         \
            const float4* xp = (const float4*)(x + (size_t)(i0 + rg * 4 + rr) * INF_ \
                                               + (kt) * 128 + oct * 8);          \
            xr[rr][0] = xp[0]; xr[rr][1] = xp[1];                                \
        }                                                                        \
    }
    #define WISSUE(kt, bb)                                                       \
    {                                                                            \
        const u32 dstB = sb + XW_SMB + (u32)(bb) * 65536u;                       \
        const unsigned char* srcB = g_wh + (size_t)(kt) * 65536;                 \
        _Pragma("unroll")                                                        \
        for (int it = 0; it < 16; it++) {                                        \
            u32 off = (u32)tid * 16u + (u32)it * 4096u;                          \
            cpa16(dstB + off, srcB + off);                                       \
        }                                                                        \
        cpa_commit();                                                            \
    }

    XLOAD(0);
    WISSUE(0, 0);

    const u32 a_row_off = (u32)((wm * 32 + (lane & 15)) * 256);
    const u32 a_hi      = (u32)(lane >> 4);
    const u32 sxor      = (u32)(lane & 7);
    const u32 b_row_off = (u32)((lane & 15) * 512 + wn * 128);

    for (int kt = 0; kt < 4; kt++) {
        const int buf = kt & 1;
        if (kt < 3) WISSUE(kt + 1, buf ^ 1);

        // pack x regs -> A smem (fp16, swizzled), single buffer
        #pragma unroll
        for (int rr = 0; rr < 4; rr++) {
            int i = rg * 4 + rr;
            uint4 o = make_uint4(packh2(xr[rr][0].x, xr[rr][0].y),
                                 packh2(xr[rr][0].z, xr[rr][0].w),
                                 packh2(xr[rr][1].x, xr[rr][1].y),
                                 packh2(xr[rr][1].z, xr[rr][1].w));
            u32 soff = (u32)i * 256u + ((((u32)oct) ^ ((u32)i & 7u)) << 4);
            *(uint4*)(smem + XW_SMA + soff) = o;
        }
        if (kt < 3) XLOAD(kt + 1);                 // prefetch next x (hidden by MMA)
        if (kt < 3) cpa_wait1(); else cpa_wait0(); // W(kt) landed
        __syncthreads();

        const u32 Abuf = sb + XW_SMA;
        const u32 Bbuf = sb + XW_SMB + (u32)buf * 65536u;
        #pragma unroll
        for (int kk = 0; kk < 8; kk++) {
            u32 afr[2][4];
            #pragma unroll
            for (int mi = 0; mi < 2; mi++) {
                u32 chunk = (u32)(kk * 2) + a_hi;
                ldsm4(afr[mi], Abuf + a_row_off + (u32)mi * 4096u
                                  + ((chunk ^ sxor) << 4));
            }
            u32 bfr[4][4];
            #pragma unroll
            for (int nb2 = 0; nb2 < 4; nb2++) {
                u32 chunk = (u32)(nb2 * 2) + a_hi;
                ldsm4t(bfr[nb2], Bbuf + (u32)(kk * 16) * 512u + b_row_off
                                    + ((chunk ^ sxor) << 4));
            }
            #pragma unroll
            for (int mi = 0; mi < 2; mi++)
                #pragma unroll
                for (int n8 = 0; n8 < 8; n8++)
                    mma16816(acc[mi][n8], afr[mi], &bfr[n8 >> 1][(n8 & 1) * 2]);
        }
        __syncthreads();
    }

    // ---- epilogue: write g_hh fp16 swz + fused s1/s2 + exp tables ----
    const int g  = lane >> 2;
    const int tq = lane & 3;
    float* sp1 = (float*)(smem);          // [4][64]
    float* sp2 = (float*)(smem + 1024);   // [4][64]

    #pragma unroll
    for (int mi = 0; mi < 2; mi++) {
        int rl0 = wm * 32 + mi * 16 + g;
        int j0r = i0 + rl0, j8r = i0 + rl0 + 8;
        float s10 = 0.f, s20 = 0.f, s18 = 0.f, s28 = 0.f;
        #pragma unroll
        for (int n8 = 0; n8 < 8; n8++) {
            int col = wn * 64 + n8 * 8 + tq * 2;
            float2 h0 = make_float2(acc[mi][n8][0], acc[mi][n8][1]);
            float2 h8 = make_float2(acc[mi][n8][2], acc[mi][n8][3]);
            u32 off0 = (u32)j0r * 512u + ((((u32)(col >> 3)) ^ ((u32)j0r & 7u)) << 4)
                     + ((u32)(col & 7)) * 2u;
            u32 off8 = (u32)j8r * 512u + ((((u32)(col >> 3)) ^ ((u32)j8r & 7u)) << 4)
                     + ((u32)(col & 7)) * 2u;
            *(u32*)(g_hh + off0) = packh2(h0.x, h0.y);
            *(u32*)(g_hh + off8) = packh2(h8.x, h8.y);
            float2 a1v = *(const float2*)(av + col);
            float2 a2v = *(const float2*)(av + OUTF + col);
            s10 += h0.x * a1v.x + h0.y * a1v.y;
            s20 += h0.x * a2v.x + h0.y * a2v.y;
            s18 += h8.x * a1v.x + h8.y * a1v.y;
            s28 += h8.x * a2v.x + h8.y * a2v.y;
        }
        #pragma unroll
        for (int m = 1; m < 4; m <<= 1) {
            s10 += __shfl_xor_sync(0xffffffffu, s10, m);
            s20 += __shfl_xor_sync(0xffffffffu, s20, m);
            s18 += __shfl_xor_sync(0xffffffffu, s18, m);
            s28 += __shfl_xor_sync(0xffffffffu, s28, m);
        }
        if (tq == 0) {
            sp1[wn * 64 + rl0] = s10;     sp2[wn * 64 + rl0] = s20;
            sp1[wn * 64 + rl0 + 8] = s18; sp2[wn * 64 + rl0 + 8] = s28;
        }
    }
    __syncthreads();
    if (tid < 64) {
        float s1 = (sp1[tid] + sp1[64 + tid]) + (sp1[128 + tid] + sp1[192 + tid]);
        float s2 = (sp2[tid] + sp2[64 + tid]) + (sp2[128 + tid] + sp2[192 + tid]);
        int row = i0 + tid;
        g_s1[row]  = s1;
        g_s2[row]  = s2;
        g_e1p[row] = __expf(s1);
        g_e1n[row] = __expf(ALPHA * s1);
        g_e2p[row] = __expf(s2);
        g_e2n[row] = __expf(ALPHA * s2);
    }
    #undef XLOAD
    #undef WISSUE
}

// ============================================================
// Kernel 3: warp-specialized fused masked-softmax + P@h
//   R9/R13 schedule VERBATIM; single change: adj for tile tp is
//   PRE-LOADED in registers, prefetch for tp+1 issued after pack(tp)
//   so its DRAM latency overlaps wait_group0 + barriers + B issue.
// ============================================================
#define KT 128
#define NTILE (NN / KT)
#define SM_ZP   0
#define SM_A    4096
#define SM_B    36864
#define SMEM_ATTN 167936
#define NTHREADS 512

__global__ void __launch_bounds__(NTHREADS) k_attn(const int* __restrict__ adj,
                                                   const float* __restrict__ bias,
                                                   float* __restrict__ out) {
    extern __shared__ __align__(16) char smem[];
    const u32 sb = smem_u32(smem);
    const int tid  = threadIdx.x;
    const int lane = tid & 31;
    const int wid  = tid >> 5;
    const int i0   = blockIdx.x * 64;
    float* zp = (float*)(smem + SM_ZP);    // zp[16][64]

    if (wid < 8) {
        // ================= CONSUMERS: MMA (unchanged) =================
        const int wn = wid & 3;
        const int wm = wid >> 2;

        float acc[2][8][4];
        #pragma unroll
        for (int mi = 0; mi < 2; mi++)
            #pragma unroll
            for (int n8 = 0; n8 < 8; n8++)
                #pragma unroll
                for (int c = 0; c < 4; c++) acc[mi][n8][c] = 0.f;

        const u32 a_row_off = (u32)((wm * 32 + (lane & 15)) * 256);
        const u32 a_hi      = (u32)(lane >> 4);
        const u32 sxor      = (u32)(lane & 7);
        const u32 b_row_off = (u32)((lane & 15) * 512 + wn * 128);

        for (int t = 0; t < NTILE; t++) {
            const int p = t & 1;
            bar_sync(1 + p, NTHREADS);   // wait full[p]

            const u32 Abuf = sb + SM_A + (u32)p * 16384u;
            const u32 Bbuf = sb + SM_B + (u32)p * 65536u;
            #pragma unroll
            for (int kk = 0; kk < 8; kk++) {
                u32 afr[2][4];
                #pragma unroll
                for (int mi = 0; mi < 2; mi++) {
                    u32 chunk = (u32)(kk * 2) + a_hi;
                    ldsm4(afr[mi], Abuf + a_row_off + (u32)mi * 4096u
                                      + ((chunk ^ sxor) << 4));
                }
                u32 bfr[4][4];
                #pragma unroll
                for (int nb2 = 0; nb2 < 4; nb2++) {
                    u32 chunk = (u32)(nb2 * 2) + a_hi;
                    ldsm4t(bfr[nb2], Bbuf + (u32)(kk * 16) * 512u + b_row_off
                                        + ((chunk ^ sxor) << 4));
                }
                #pragma unroll
                for (int mi = 0; mi < 2; mi++)
                    #pragma unroll
                    for (int n8 = 0; n8 < 8; n8++)
                        mma16816(acc[mi][n8], afr[mi], &bfr[n8 >> 1][(n8 & 1) * 2]);
            }
            bar_arrive(3 + p, NTHREADS); // signal empty[p]
        }

        __syncthreads();   // producers have written zp

        // ---- epilogue: out = acc/Z + bias ----
        const int g  = lane >> 2;
        const int tq = lane & 3;
        #pragma unroll
        for (int mi = 0; mi < 2; mi++) {
            int rl0 = wm * 32 + mi * 16 + g;
            float z0 = 0.f, z8 = 0.f;
            #pragma unroll
            for (int o = 0; o < 16; o++) {
                z0 += zp[o * 64 + rl0];
                z8 += zp[o * 64 + rl0 + 8];
            }
            float inv0 = (z0 > 0.f) ? 1.0f / z0 : 0.f;
            float inv8 = (z8 > 0.f) ? 1.0f / z8 : 0.f;
            float* o0 = out + (size_t)(i0 + rl0) * OUTF;
            float* o8 = out + (size_t)(i0 + rl0 + 8) * OUTF;
            #pragma unroll
            for (int n8 = 0; n8 < 8; n8++) {
                int col = wn * 64 + n8 * 8 + tq * 2;
                float2 b2 = *(const float2*)(bias + col);
                float2 r0, r8;
                r0.x = acc[mi][n8][0] * inv0 + b2.x;
                r0.y = acc[mi][n8][1] * inv0 + b2.y;
                r8.x = acc[mi][n8][2] * inv8 + b2.x;
                r8.y = acc[mi][n8][3] * inv8 + b2.y;
                *(float2*)(o0 + col) = r0;
                *(float2*)(o8 + col) = r8;
            }
        }
    } else {
        // ======= PRODUCERS: adj PRE-LOADED; schedule otherwise R9 =======
        const int ptid = tid - 256;        // 0..255
        const int oct  = ptid & 15;        // j-octet: j = oct*8 .. +7
        const int rg   = ptid >> 4;        // 0..15 -> rows rg*4 .. +3
        float s1v[4], e1pv[4], e1nv[4], zacc[4];
        #pragma unroll
        for (int rr = 0; rr < 4; rr++) {
            int i = rg * 4 + rr;
            s1v[rr]  = g_s1[i0 + i];
            e1pv[rr] = g_e1p[i0 + i];
            e1nv[rr] = g_e1n[i0 + i];
            zacc[rr] = 0.f;
        }

        // adj registers for the CURRENT tile (prefetched one tile ahead)
        int4 adjr[4][2];
        #pragma unroll
        for (int rr = 0; rr < 4; rr++) {
            const int* ar = adj + (size_t)(i0 + rg * 4 + rr) * NN + oct * 8;
            adjr[rr][0] = *(const int4*)ar;
            adjr[rr][1] = *(const int4*)(ar + 4);
        }

        for (int tp = 0; tp < NTILE; tp++) {
            const int p = tp & 1;
            if (tp >= 2) bar_sync(3 + p, NTHREADS);   // wait empty[p]

            // ---- issue B cp.async (64KB pre-swizzled fp16 h) ----
            {
                const u32 dstB = sb + SM_B + (u32)p * 65536u;
                const unsigned char* src = g_hh + (size_t)tp * 65536 + ptid * 16;
                #pragma unroll
                for (int it = 0; it < 16; it++)
                    cpa16(dstB + (u32)ptid * 16u + (u32)it * 4096u, src + it * 4096);
                cpa_commit();
            }

            // ---- pack P tile from PRE-LOADED adj regs ----
            {
                const int jb = tp * KT + oct * 8;
                float4 s2a = *(const float4*)(g_s2  + jb);
                float4 s2b = *(const float4*)(g_s2  + jb + 4);
                float4 epa = *(const float4*)(g_e2p + jb);
                float4 epb = *(const float4*)(g_e2p + jb + 4);
                float4 ena = *(const float4*)(g_e2n + jb);
                float4 enb = *(const float4*)(g_e2n + jb + 4);
                char* Ah = smem + SM_A + p * 16384;
                #pragma unroll
                for (int rr = 0; rr < 4; rr++) {
                    int i = rg * 4 + rr;
                    int4 a0 = adjr[rr][0];
                    int4 a1 = adjr[rr][1];
                    float s1 = s1v[rr], ep = e1pv[rr], en = e1nv[rr];
                    float p0 = (a0.x > 0) ? ((s1 + s2a.x > 0.f) ? ep * epa.x : en * ena.x) : 0.f;
                    float p1 = (a0.y > 0) ? ((s1 + s2a.y > 0.f) ? ep * epa.y : en * ena.y) : 0.f;
                    float p2 = (a0.z > 0) ? ((s1 + s2a.z > 0.f) ? ep * epa.z : en * ena.z) : 0.f;
                    float p3 = (a0.w > 0) ? ((s1 + s2a.w > 0.f) ? ep * epa.w : en * ena.w) : 0.f;
                    float p4 = (a1.x > 0) ? ((s1 + s2b.x > 0.f) ? ep * epb.x : en * enb.x) : 0.f;
                    float p5 = (a1.y > 0) ? ((s1 + s2b.y > 0.f) ? ep * epb.y : en * enb.y) : 0.f;
                    float p6 = (a1.z > 0) ? ((s1 + s2b.z > 0.f) ? ep * epb.z : en * enb.z) : 0.f;
                    float p7 = (a1.w > 0) ? ((s1 + s2b.w > 0.f) ? ep * epb.w : en * enb.w) : 0.f;
                    zacc[rr] += ((p0 + p1) + (p2 + p3)) + ((p4 + p5) + (p6 + p7));
                    uint4 o = make_uint4(packh2(p0, p1), packh2(p2, p3),
                                         packh2(p4, p5), packh2(p6, p7));
                    u32 soff = (u32)i * 256u + ((((u32)oct) ^ ((u32)i & 7u)) << 4);
                    *(uint4*)(Ah + soff) = o;
                }
            }

            // ---- prefetch adj for tile tp+1 (latency hidden by wait0+barriers) ----
            if (tp + 1 < NTILE) {
                const int jn = (tp + 1) * KT + oct * 8;
                #pragma unroll
                for (int rr = 0; rr < 4; rr++) {
                    const int* ar = adj + (size_t)(i0 + rg * 4 + rr) * NN + jn;
                    adjr[rr][0] = *(const int4*)ar;
                    adjr[rr][1] = *(const int4*)(ar + 4);
                }
            }

            cpa_wait0();                  // B[p] landed
            bar_arrive(1 + p, NTHREADS);  // signal full[p]
        }

        #pragma unroll
        for (int rr = 0; rr < 4; rr++)
            zp[oct * 64 + rg * 4 + rr] = zacc[rr];
        __syncthreads();
    }
}

// ============================================================
extern "C" void kernel_launch(void* const* d_in, const int* in_sizes, int n_in,
                              void* d_out, int out_size) {
    (void)in_sizes; (void)n_in; (void)out_size;
    const float* x    = (const float*)d_in[0];
    const int*   adj  = (const int*)  d_in[1];
    const float* W    = (const float*)d_in[2];
    const float* a    = (const float*)d_in[3];
    const float* bias = (const float*)d_in[4];
    float* out = (float*)d_out;

    cudaFuncSetAttribute(k_xw_mma, cudaFuncAttributeMaxDynamicSharedMemorySize, XW_SMEM);
    cudaFuncSetAttribute(k_attn,   cudaFuncAttributeMaxDynamicSharedMemorySize, SMEM_ATTN);

    k_cvtw  <<<64, 256>>>(W);
    k_xw_mma<<<NN / 64, 256, XW_SMEM>>>(x, a);
    k_attn  <<<NN / 64, NTHREADS, SMEM_ATTN>>>(adj, bias, out);
}

// round 17
// speedup vs baseline: 1.3606x; 1.0127x over previous
#include <cuda_runtime.h>
#include <cuda_fp16.h>
#include <cstdint>
#include <cstddef>

#define NN    8192
#define INF_  512
#define OUTF  256
#define ALPHA 0.2f

typedef unsigned long long u64;
typedef unsigned int u32;

// ---------------- scratch globals (no allocs allowed) ----------------
__device__ float g_s1[NN];
__device__ float g_s2[NN];
__device__ float g_e1p[NN];   // exp(s1)
__device__ float g_e1n[NN];   // exp(ALPHA*s1)
__device__ float g_e2p[NN];   // exp(s2)
__device__ float g_e2n[NN];   // exp(ALPHA*s2)
// h as fp16, PRE-SWIZZLED B-layout: byte(j,n) = j*512 + (((n>>3)^(j&7))<<4) + (n&7)*2
__device__ __align__(16) unsigned char g_hh[(size_t)NN * 512];
// W as fp16, PRE-SWIZZLED B-layout per 128-k tile
__device__ __align__(16) unsigned char g_wh[(size_t)INF_ * 512];

// ---------------- mma / ldmatrix / cp.async / barrier helpers ----------------
__device__ __forceinline__ u32 smem_u32(const void* p) {
    u32 a;
    asm("{ .reg .u64 t; cvta.to.shared.u64 t, %1; cvt.u32.u64 %0, t; }"
        : "=r"(a) : "l"(p));
    return a;
}
__device__ __forceinline__ void ldsm4(u32* r, u32 addr) {
    asm volatile("ldmatrix.sync.aligned.m8n8.x4.shared.b16 {%0,%1,%2,%3}, [%4];"
                 : "=r"(r[0]), "=r"(r[1]), "=r"(r[2]), "=r"(r[3]) : "r"(addr));
}
__device__ __forceinline__ void ldsm4t(u32* r, u32 addr) {
    asm volatile("ldmatrix.sync.aligned.m8n8.x4.trans.shared.b16 {%0,%1,%2,%3}, [%4];"
                 : "=r"(r[0]), "=r"(r[1]), "=r"(r[2]), "=r"(r[3]) : "r"(addr));
}
__device__ __forceinline__ void mma16816(float* d, const u32* a, const u32* b) {
    asm volatile(
        "mma.sync.aligned.m16n8k16.row.col.f32.f16.f16.f32 "
        "{%0,%1,%2,%3}, {%4,%5,%6,%7}, {%8,%9}, {%0,%1,%2,%3};"
        : "+f"(d[0]), "+f"(d[1]), "+f"(d[2]), "+f"(d[3])
        : "r"(a[0]), "r"(a[1]), "r"(a[2]), "r"(a[3]), "r"(b[0]), "r"(b[1]));
}
__device__ __forceinline__ void cpa16(u32 dst, const void* src) {
    asm volatile("cp.async.cg.shared.global [%0], [%1], 16;"
                 :: "r"(dst), "l"(src) : "memory");
}
__device__ __forceinline__ void cpa_commit() {
    asm volatile("cp.async.commit_group;" ::: "memory");
}
__device__ __forceinline__ void cpa_wait0() {
    asm volatile("cp.async.wait_group 0;" ::: "memory");
}
__device__ __forceinline__ void cpa_wait1() {
    asm volatile("cp.async.wait_group 1;" ::: "memory");
}
__device__ __forceinline__ u32 packh2(float a, float b) {
    __half2 h = __floats2half2_rn(a, b);
    return *reinterpret_cast<u32*>(&h);
}
__device__ __forceinline__ void bar_sync(int id, int cnt) {
    asm volatile("bar.sync %0, %1;" :: "r"(id), "r"(cnt) : "memory");
}
__device__ __forceinline__ void bar_arrive(int id, int cnt) {
    asm volatile("bar.arrive %0, %1;" :: "r"(id), "r"(cnt) : "memory");
}

// ============================================================
// Kernel 0: convert W -> g_wh (B-layout) only (x fused into k_xw_mma)
// ============================================================
__global__ void __launch_bounds__(256) k_cvtw(const float* __restrict__ W) {
    int gid = blockIdx.x * 256 + threadIdx.x;     // 16384 total
    int k = gid >> 5;
    int c = gid & 31;
    int ktile = k >> 7, kl = k & 127;
    const float4* src = (const float4*)(W + (size_t)k * OUTF + c * 8);
    float4 a = src[0], b = src[1];
    uint4 o = make_uint4(packh2(a.x, a.y), packh2(a.z, a.w),
                         packh2(b.x, b.y), packh2(b.z, b.w));
    u32 off = (u32)ktile * 65536u + (u32)kl * 512u
            + ((((u32)c) ^ ((u32)kl & 7u)) << 4);
    *(uint4*)(g_wh + off) = o;
}

// ============================================================
// Kernel 1: h = x @ W via fp16 mma.sync; x converted IN-KERNEL.
//   Writes g_hh (fp16 swz); FUSED s1/s2 + exp tables. (R15/R16 verbatim)
// ============================================================
#define XW_SMA 0
#define XW_SMB 16384
#define XW_SMEM 147456

__global__ void __launch_bounds__(256) k_xw_mma(const float* __restrict__ x,
                                                const float* __restrict__ av) {
    extern __shared__ __align__(16) char smem[];
    const u32 sb = smem_u32(smem);
    const int tid  = threadIdx.x;
    const int lane = tid & 31;
    const int wid  = tid >> 5;
    const int wn   = wid & 3;
    const int wm   = wid >> 2;
    const int i0   = blockIdx.x * 64;

    const int oct = tid & 15;      // k-octet within tile
    const int rg  = tid >> 4;      // row group (4 rows)

    float acc[2][8][4];
    #pragma unroll
    for (int mi = 0; mi < 2; mi++)
        #pragma unroll
        for (int n8 = 0; n8 < 8; n8++)
            #pragma unroll
            for (int c = 0; c < 4; c++) acc[mi][n8][c] = 0.f;

    float4 xr[4][2];
    #define XLOAD(kt)                                                            \
    {                                                                            \
        _Pragma("unroll")                                                        \
        for (int rr = 0; rr < 4; rr++) {                                         \
            const float4* xp = (const float4*)(x + (size_t)(i0 + rg * 4 + rr) * INF_ \
                                               + (kt) * 128 + oct * 8);          \
            xr[rr][0] = xp[0]; xr[rr][1] = xp[1];                                \
        }                                                                        \
    }
    #define WISSUE(kt, bb)                                                       \
    {                                                                            \
        const u32 dstB = sb + XW_SMB + (u32)(bb) * 65536u;                       \
        const unsigned char* srcB = g_wh + (size_t)(kt) * 65536;                 \
        _Pragma("unroll")                                                        \
        for (int it = 0; it < 16; it++) {                                        \
            u32 off = (u32)tid * 16u + (u32)it * 4096u;                          \
            cpa16(dstB + off, srcB + off);                                       \
        }                                                                        \
        cpa_commit();                                                            \
    }

    XLOAD(0);
    WISSUE(0, 0);

    const u32 a_row_off = (u32)((wm * 32 + (lane & 15)) * 256);
    const u32 a_hi      = (u32)(lane >> 4);
    const u32 sxor      = (u32)(lane & 7);
    const u32 b_row_off = (u32)((lane & 15) * 512 + wn * 128);

    for (int kt = 0; kt < 4; kt++) {
        const int buf = kt & 1;
        if (kt < 3) WISSUE(kt + 1, buf ^ 1);

        // pack x regs -> A smem (fp16, swizzled), single buffer
        #pragma unroll
        for (int rr = 0; rr < 4; rr++) {
            int i = rg * 4 + rr;
            uint4 o = make_uint4(packh2(xr[rr][0].x, xr[rr][0].y),
                                 packh2(xr[rr][0].z, xr[rr][0].w),
                                 packh2(xr[rr][1].x, xr[rr][1].y),
                                 packh2(xr[rr][1].z, xr[rr][1].w));
            u32 soff = (u32)i * 256u + ((((u32)oct) ^ ((u32)i & 7u)) << 4);
            *(uint4*)(smem + XW_SMA + soff) = o;
        }
        if (kt < 3) XLOAD(kt + 1);                 // prefetch next x (hidden by MMA)
        if (kt < 3) cpa_wait1(); else cpa_wait0(); // W(kt) landed
        __syncthreads();

        const u32 Abuf = sb + XW_SMA;
        const u32 Bbuf = sb + XW_SMB + (u32)buf * 65536u;
        #pragma unroll
        for (int kk = 0; kk < 8; kk++) {
            u32 afr[2][4];
            #pragma unroll
            for (int mi = 0; mi < 2; mi++) {
                u32 chunk = (u32)(kk * 2) + a_hi;
                ldsm4(afr[mi], Abuf + a_row_off + (u32)mi * 4096u
                                  + ((chunk ^ sxor) << 4));
            }
            u32 bfr[4][4];
            #pragma unroll
            for (int nb2 = 0; nb2 < 4; nb2++) {
                u32 chunk = (u32)(nb2 * 2) + a_hi;
                ldsm4t(bfr[nb2], Bbuf + (u32)(kk * 16) * 512u + b_row_off
                                    + ((chunk ^ sxor) << 4));
            }
            #pragma unroll
            for (int mi = 0; mi < 2; mi++)
                #pragma unroll
                for (int n8 = 0; n8 < 8; n8++)
                    mma16816(acc[mi][n8], afr[mi], &bfr[n8 >> 1][(n8 & 1) * 2]);
        }
        __syncthreads();
    }

    // ---- epilogue: write g_hh fp16 swz + fused s1/s2 + exp tables ----
    const int g  = lane >> 2;
    const int tq = lane & 3;
    float* sp1 = (float*)(smem);          // [4][64]
    float* sp2 = (float*)(smem + 1024);   // [4][64]

    #pragma unroll
    for (int mi = 0; mi < 2; mi++) {
        int rl0 = wm * 32 + mi * 16 + g;
        int j0r = i0 + rl0, j8r = i0 + rl0 + 8;
        float s10 = 0.f, s20 = 0.f, s18 = 0.f, s28 = 0.f;
        #pragma unroll
        for (int n8 = 0; n8 < 8; n8++) {
            int col = wn * 64 + n8 * 8 + tq * 2;
            float2 h0 = make_float2(acc[mi][n8][0], acc[mi][n8][1]);
            float2 h8 = make_float2(acc[mi][n8][2], acc[mi][n8][3]);
            u32 off0 = (u32)j0r * 512u + ((((u32)(col >> 3)) ^ ((u32)j0r & 7u)) << 4)
                     + ((u32)(col & 7)) * 2u;
            u32 off8 = (u32)j8r * 512u + ((((u32)(col >> 3)) ^ ((u32)j8r & 7u)) << 4)
                     + ((u32)(col & 7)) * 2u;
            *(u32*)(g_hh + off0) = packh2(h0.x, h0.y);
            *(u32*)(g_hh + off8) = packh2(h8.x, h8.y);
            float2 a1v = *(const float2*)(av + col);
            float2 a2v = *(const float2*)(av + OUTF + col);
            s10 += h0.x * a1v.x + h0.y * a1v.y;
            s20 += h0.x * a2v.x + h0.y * a2v.y;
            s18 += h8.x * a1v.x + h8.y * a1v.y;
            s28 += h8.x * a2v.x + h8.y * a2v.y;
        }
        #pragma unroll
        for (int m = 1; m < 4; m <<= 1) {
            s10 += __shfl_xor_sync(0xffffffffu, s10, m);
            s20 += __shfl_xor_sync(0xffffffffu, s20, m);
            s18 += __shfl_xor_sync(0xffffffffu, s18, m);
            s28 += __shfl_xor_sync(0xffffffffu, s28, m);
        }
        if (tq == 0) {
            sp1[wn * 64 + rl0] = s10;     sp2[wn * 64 + rl0] = s20;
            sp1[wn * 64 + rl0 + 8] = s18; sp2[wn * 64 + rl0 + 8] = s28;
        }
    }
    __syncthreads();
    if (tid < 64) {
        float s1 = (sp1[tid] + sp1[64 + tid]) + (sp1[128 + tid] + sp1[192 + tid]);
        float s2 = (sp2[tid] + sp2[64 + tid]) + (sp2[128 + tid] + sp2[192 + tid]);
        int row = i0 + tid;
        g_s1[row]  = s1;
        g_s2[row]  = s2;
        g_e1p[row] = __expf(s1);
        g_e1n[row] = __expf(ALPHA * s1);
        g_e2p[row] = __expf(s2);
        g_e2n[row] = __expf(ALPHA * s2);
    }
    #undef XLOAD
    #undef WISSUE
}

// ============================================================
// Kernel 3: warp-specialized fused masked-softmax + P@h
//   R16 verbatim EXCEPT: consumer A-fragments are software-pipelined
//   across kk (2-slot ring, +8 regs) — ldsm A(kk+1) issued before
//   ldsm B(kk) so the B-wait + mma burst hide A's latency.
// ============================================================
#define KT 128
#define NTILE (NN / KT)
#define SM_ZP   0
#define SM_A    4096
#define SM_B    36864
#define SMEM_ATTN 167936
#define NTHREADS 512

__global__ void __launch_bounds__(NTHREADS) k_attn(const int* __restrict__ adj,
                                                   const float* __restrict__ bias,
                                                   float* __restrict__ out) {
    extern __shared__ __align__(16) char smem[];
    const u32 sb = smem_u32(smem);
    const int tid  = threadIdx.x;
    const int lane = tid & 31;
    const int wid  = tid >> 5;
    const int i0   = blockIdx.x * 64;
    float* zp = (float*)(smem + SM_ZP);    // zp[16][64]

    if (wid < 8) {
        // ================= CONSUMERS: MMA (A-frag pipelined) =================
        const int wn = wid & 3;
        const int wm = wid >> 2;

        float acc[2][8][4];
        #pragma unroll
        for (int mi = 0; mi < 2; mi++)
            #pragma unroll
            for (int n8 = 0; n8 < 8; n8++)
                #pragma unroll
                for (int c = 0; c < 4; c++) acc[mi][n8][c] = 0.f;

        const u32 a_row_off = (u32)((wm * 32 + (lane & 15)) * 256);
        const u32 a_hi      = (u32)(lane >> 4);
        const u32 sxor      = (u32)(lane & 7);
        const u32 b_row_off = (u32)((lane & 15) * 512 + wn * 128);

        for (int t = 0; t < NTILE; t++) {
            const int p = t & 1;
            bar_sync(1 + p, NTHREADS);   // wait full[p]

            const u32 Abuf = sb + SM_A + (u32)p * 16384u;
            const u32 Bbuf = sb + SM_B + (u32)p * 65536u;

            u32 afr[2][2][4];   // [slot][mi][4] — A-fragment ring
            #define LDA(kkv, sl)                                                  \
            {                                                                     \
                _Pragma("unroll")                                                 \
                for (int mi = 0; mi < 2; mi++) {                                  \
                    u32 chunk = (u32)((kkv) * 2) + a_hi;                          \
                    ldsm4(afr[sl][mi], Abuf + a_row_off + (u32)mi * 4096u         \
                                          + ((chunk ^ sxor) << 4));               \
                }                                                                 \
            }

            LDA(0, 0);
            #pragma unroll
            for (int kk = 0; kk < 8; kk++) {
                const int sl = kk & 1;
                if (kk < 7) LDA(kk + 1, sl ^ 1);   // prefetch A for next kk
                u32 bfr[4][4];
                #pragma unroll
                for (int nb2 = 0; nb2 < 4; nb2++) {
                    u32 chunk = (u32)(nb2 * 2) + a_hi;
                    ldsm4t(bfr[nb2], Bbuf + (u32)(kk * 16) * 512u + b_row_off
                                        + ((chunk ^ sxor) << 4));
                }
                #pragma unroll
                for (int mi = 0; mi < 2; mi++)
                    #pragma unroll
                    for (int n8 = 0; n8 < 8; n8++)
                        mma16816(acc[mi][n8], afr[sl][mi],
                                 &bfr[n8 >> 1][(n8 & 1) * 2]);
            }
            #undef LDA

            bar_arrive(3 + p, NTHREADS); // signal empty[p]
        }

        __syncthreads();   // producers have written zp

        // ---- epilogue: out = acc/Z + bias ----
        const int g  = lane >> 2;
        const int tq = lane & 3;
        #pragma unroll
        for (int mi = 0; mi < 2; mi++) {
            int rl0 = wm * 32 + mi * 16 + g;
            float z0 = 0.f, z8 = 0.f;
            #pragma unroll
            for (int o = 0; o < 16; o++) {
                z0 += zp[o * 64 + rl0];
                z8 += zp[o * 64 + rl0 + 8];
            }
            float inv0 = (z0 > 0.f) ? 1.0f / z0 : 0.f;
            float inv8 = (z8 > 0.f) ? 1.0f / z8 : 0.f;
            float* o0 = out + (size_t)(i0 + rl0) * OUTF;
            float* o8 = out + (size_t)(i0 + rl0 + 8) * OUTF;
            #pragma unroll
            for (int n8 = 0; n8 < 8; n8++) {
                int col = wn * 64 + n8 * 8 + tq * 2;
                float2 b2 = *(const float2*)(bias + col);
                float2 r0, r8;
                r0.x = acc[mi][n8][0] * inv0 + b2.x;
                r0.y = acc[mi][n8][1] * inv0 + b2.y;
                r8.x = acc[mi][n8][2] * inv8 + b2.x;
                r8.y = acc[mi][n8][3] * inv8 + b2.y;
                *(float2*)(o0 + col) = r0;
                *(float2*)(o8 + col) = r8;
            }
        }
    } else {
        // ======= PRODUCERS: R16 verbatim (adj pre-loaded, R9 schedule) =======
        const int ptid = tid - 256;        // 0..255
        const int oct  = ptid & 15;        // j-octet: j = oct*8 .. +7
        const int rg   = ptid >> 4;        // 0..15 -> rows rg*4 .. +3
        float s1v[4], e1pv[4], e1nv[4], zacc[4];
        #pragma unroll
        for (int rr = 0; rr < 4; rr++) {
            int i = rg * 4 + rr;
            s1v[rr]  = g_s1[i0 + i];
            e1pv[rr] = g_e1p[i0 + i];
            e1nv[rr] = g_e1n[i0 + i];
            zacc[rr] = 0.f;
        }

        int4 adjr[4][2];
        #pragma unroll
        for (int rr = 0; rr < 4; rr++) {
            const int* ar = adj + (size_t)(i0 + rg * 4 + rr) * NN + oct * 8;
            adjr[rr][0] = *(const int4*)ar;
            adjr[rr][1] = *(const int4*)(ar + 4);
        }

        for (int tp = 0; tp < NTILE; tp++) {
            const int p = tp & 1;
            if (tp >= 2) bar_sync(3 + p, NTHREADS);   // wait empty[p]

            // ---- issue B cp.async (64KB pre-swizzled fp16 h) ----
            {
                const u32 dstB = sb + SM_B + (u32)p * 65536u;
                const unsigned char* src = g_hh + (size_t)tp * 65536 + ptid * 16;
                #pragma unroll
                for (int it = 0; it < 16; it++)
                    cpa16(dstB + (u32)ptid * 16u + (u32)it * 4096u, src + it * 4096);
                cpa_commit();
            }

            // ---- pack P tile from PRE-LOADED adj regs ----
            {
                const int jb = tp * KT + oct * 8;
                float4 s2a = *(const float4*)(g_s2  + jb);
                float4 s2b = *(const float4*)(g_s2  + jb + 4);
                float4 epa = *(const float4*)(g_e2p + jb);
                float4 epb = *(const float4*)(g_e2p + jb + 4);
                float4 ena = *(const float4*)(g_e2n + jb);
                float4 enb = *(const float4*)(g_e2n + jb + 4);
                char* Ah = smem + SM_A + p * 16384;
                #pragma unroll
                for (int rr = 0; rr < 4; rr++) {
                    int i = rg * 4 + rr;
                    int4 a0 = adjr[rr][0];
                    int4 a1 = adjr[rr][1];
                    float s1 = s1v[rr], ep = e1pv[rr], en = e1nv[rr];
                    float p0 = (a0.x > 0) ? ((s1 + s2a.x > 0.f) ? ep * epa.x : en * ena.x) : 0.f;
                    float p1 = (a0.y > 0) ? ((s1 + s2a.y > 0.f) ? ep * epa.y : en * ena.y) : 0.f;
                    float p2 = (a0.z > 0) ? ((s1 + s2a.z > 0.f) ? ep * epa.z : en * ena.z) : 0.f;
                    float p3 = (a0.w > 0) ? ((s1 + s2a.w > 0.f) ? ep * epa.w : en * ena.w) : 0.f;
                    float p4 = (a1.x > 0) ? ((s1 + s2b.x > 0.f) ? ep * epb.x : en * enb.x) : 0.f;
                    float p5 = (a1.y > 0) ? ((s1 + s2b.y > 0.f) ? ep * epb.y : en * enb.y) : 0.f;
                    float p6 = (a1.z > 0) ? ((s1 + s2b.z > 0.f) ? ep * epb.z : en * enb.z) : 0.f;
                    float p7 = (a1.w > 0) ? ((s1 + s2b.w > 0.f) ? ep * epb.w : en * enb.w) : 0.f;
                    zacc[rr] += ((p0 + p1) + (p2 + p3)) + ((p4 + p5) + (p6 + p7));
                    uint4 o = make_uint4(packh2(p0, p1), packh2(p2, p3),
                                         packh2(p4, p5), packh2(p6, p7));
                    u32 soff = (u32)i * 256u + ((((u32)oct) ^ ((u32)i & 7u)) << 4);
                    *(uint4*)(Ah + soff) = o;
                }
            }

            // ---- prefetch adj for tile tp+1 ----
            if (tp + 1 < NTILE) {
                const int jn = (tp + 1) * KT + oct * 8;
                #pragma unroll
                for (int rr = 0; rr < 4; rr++) {
                    const int* ar = adj + (size_t)(i0 + rg * 4 + rr) * NN + jn;
                    adjr[rr][0] = *(const int4*)ar;
                    adjr[rr][1] = *(const int4*)(ar + 4);
                }
            }

            cpa_wait0();                  // B[p] landed
            bar_arrive(1 + p, NTHREADS);  // signal full[p]
        }

        #pragma unroll
        for (int rr = 0; rr < 4; rr++)
            zp[oct * 64 + rg * 4 + rr] = zacc[rr];
        __syncthreads();
    }
}

// ============================================================
extern "C" void kernel_launch(void* const* d_in, const int* in_sizes, int n_in,
                              void* d_out, int out_size) {
    (void)in_sizes; (void)n_in; (void)out_size;
    const float* x    = (const float*)d_in[0];
    const int*   adj  = (const int*)  d_in[1];
    const float* W    = (const float*)d_in[2];
    const float* a    = (const float*)d_in[3];
    const float* bias = (const float*)d_in[4];
    float* out = (float*)d_out;

    cudaFuncSetAttribute(k_xw_mma, cudaFuncAttributeMaxDynamicSharedMemorySize, XW_SMEM);
    cudaFuncSetAttribute(k_attn,   cudaFuncAttributeMaxDynamicSharedMemorySize, SMEM_ATTN);

    k_cvtw  <<<64, 256>>>(W);
    k_xw_mma<<<NN / 64, 256, XW_SMEM>>>(x, a);
    k_attn  <<<NN / 64, NTHREADS, SMEM_ATTN>>>(adj, bias, out);
}